// round 7
// baseline (speedup 1.0000x reference)
#include <cuda_runtime.h>
#include <cstdint>

// ============================================================================
// BiSDA_3977139716506 — exact algebraic simplification (proof in R2).
//
// The final LIF (tau=2, V_TH=1, v_reset=0) receives inputs in [0,1]; its
// membrane obeys v_t <= 1 - 2^-t < 1, so it can never fire: its output is
// exactly zero for every input. Then pw @ 0 = 0 and BatchNorm(0) = beta:
//
//     reference(...) == broadcast(p_beta[c]) over [T=4, B=2, C=128, 8,32,32]
//
// Verified rel_err = 0.0 in R1 (full compute), R2, R3, R5 (broadcast).
//
// R5 lesson: coalesced STG configs all hit ~8 us (4.2 TB/s) with L2 at 36%
// and issue at 12% — the generic per-thread store path is the floor, not L2.
// This round routes writes through the TMA engine instead: each CTA fills a
// 32 KB smem buffer with beta[c] (one output channel block = exactly 32 KB)
// and issues a single cp.async.bulk store. 1024 CTAs x 32 KB = 33.5 MB.
// ============================================================================

__global__ void __launch_bounds__(256) tma_broadcast_kernel(
    const float* __restrict__ p_beta, float* __restrict__ out)
{
    __shared__ alignas(128) float4 buf[2048];      // 32 KB
    int b = blockIdx.x;                            // channel block [0,1024)
    int tid = threadIdx.x;

    float v = __ldg(&p_beta[b & 127]);             // c = b % 128
    float4 f = make_float4(v, v, v, v);
#pragma unroll
    for (int j = 0; j < 8; j++)                    // lane-contiguous STS.128
        buf[j * 256 + tid] = f;
    __syncthreads();
    asm volatile("fence.proxy.async;" ::: "memory");   // order STS before TMA read

    if (tid == 0) {
        uint64_t gaddr = (uint64_t)(out + (size_t)b * 8192);
        uint32_t saddr;
        asm("{ .reg .u64 t; cvta.to.shared.u64 t, %1; cvt.u32.u64 %0, t; }"
            : "=r"(saddr) : "l"(buf));
        asm volatile(
            "cp.async.bulk.global.shared::cta.bulk_group [%0], [%1], %2;"
            :: "l"(gaddr), "r"(saddr), "r"(32768u) : "memory");
        asm volatile("cp.async.bulk.commit_group;" ::: "memory");
        asm volatile("cp.async.bulk.wait_group 0;" ::: "memory");
    }
}

extern "C" void kernel_launch(void* const* d_in, const int* in_sizes, int n_in,
                              void* d_out, int out_size)
{
    // metadata order: x, qw, q_gamma, q_beta, kw, k_gamma, k_beta,
    //                 v_gamma, v_beta, pw, p_gamma, p_beta
    const float* p_beta = (const float*)d_in[11];
    float* out = (float*)d_out;

    // One CTA per 32 KB channel block: [T=4][B=2][C=128] -> 1024 blocks.
    tma_broadcast_kernel<<<1024, 256>>>(p_beta, out);
}